// round 1
// baseline (speedup 1.0000x reference)
#include <cuda_runtime.h>
#include <cstdint>

// Problem dims (fixed by the reference)
#define NB 512
#define ND 512
#define NC 200000

static constexpr float cCOS_M  =  0.87758256189037271f;  // cos(0.5)
static constexpr float cSIN_M  =  0.47942553860420301f;  // sin(0.5)
static constexpr float cTHRESH = -0.87758256189037271f;  // cos(pi-0.5)
static constexpr float cMM     =  0.23971276930210150f;  // sin(pi-0.5)*0.5
static constexpr float cS      =  64.0f;
static constexpr float cEPS    =  1e-12f;

// Scratch (device globals; no allocation allowed)
__device__ __align__(16) float g_fn[NB * ND];     // normalized feats (fp32)
__device__ float g_invw[NC];                      // 1/max(||w_c||, eps)
__device__ float g_tl[NB];                        // target logits (fp32 exact)
__device__ float g_cosm[NB];                      // cos_theta_m per row
__device__ float g_final[NB];                     // final target logit per row
__device__ float g_tnew;

// ---------------------------------------------------------------------------
// Kernel 1: L2-normalize feats rows (fp32)
// ---------------------------------------------------------------------------
__global__ void k_norm_feats(const float* __restrict__ feats) {
    int b = blockIdx.x;
    int tid = threadIdx.x;
    const float* x = feats + (size_t)b * ND;
    float s = 0.f;
    for (int i = tid; i < ND; i += 128) { float v = x[i]; s += v * v; }
    for (int o = 16; o; o >>= 1) s += __shfl_xor_sync(0xffffffffu, s, o);
    __shared__ float red[4];
    __shared__ float sinv;
    if ((tid & 31) == 0) red[tid >> 5] = s;
    __syncthreads();
    if (tid == 0) {
        float tot = red[0] + red[1] + red[2] + red[3];
        sinv = 1.0f / fmaxf(sqrtf(tot), cEPS);
    }
    __syncthreads();
    float inv = sinv;
    for (int i = tid; i < ND; i += 128) g_fn[(size_t)b * ND + i] = x[i] * inv;
}

// ---------------------------------------------------------------------------
// Kernel 2: per-class inverse weight norms (warp per row, float4 loads)
// ---------------------------------------------------------------------------
__global__ void k_wnorm(const float* __restrict__ w) {
    int row = blockIdx.x * (blockDim.x >> 5) + (threadIdx.x >> 5);
    if (row >= NC) return;
    int lane = threadIdx.x & 31;
    const float4* p = reinterpret_cast<const float4*>(w + (size_t)row * ND);
    float s = 0.f;
#pragma unroll
    for (int i = 0; i < 4; i++) {
        float4 v = p[lane + 32 * i];
        s += v.x * v.x + v.y * v.y + v.z * v.z + v.w * v.w;
    }
    for (int o = 16; o; o >>= 1) s += __shfl_xor_sync(0xffffffffu, s, o);
    if (lane == 0) g_invw[row] = 1.0f / fmaxf(sqrtf(s), cEPS);
}

// ---------------------------------------------------------------------------
// Kernel 3: target logits in full fp32 (exact path for the scattered column)
// ---------------------------------------------------------------------------
__global__ void k_target(const float* __restrict__ w, const int* __restrict__ labels) {
    int b = blockIdx.x;
    int tid = threadIdx.x;
    int c = labels[b];
    const float* wr = w + (size_t)c * ND;
    const float* f = g_fn + (size_t)b * ND;
    float s = 0.f;
    for (int i = tid; i < ND; i += 128) s += f[i] * wr[i];
    for (int o = 16; o; o >>= 1) s += __shfl_xor_sync(0xffffffffu, s, o);
    __shared__ float red[4];
    if ((tid & 31) == 0) red[tid >> 5] = s;
    __syncthreads();
    if (tid == 0) {
        float tot = red[0] + red[1] + red[2] + red[3];
        float tl = fminf(fmaxf(tot * g_invw[c], -1.0f), 1.0f);
        g_tl[b] = tl;
    }
}

// ---------------------------------------------------------------------------
// Kernel 4: t_new, cos_theta_m, final_target_logit (1 block, 512 threads)
// ---------------------------------------------------------------------------
__global__ void k_scalars(const float* __restrict__ t) {
    int b = threadIdx.x;
    float tl = g_tl[b];
    float s = tl;
    for (int o = 16; o; o >>= 1) s += __shfl_xor_sync(0xffffffffu, s, o);
    __shared__ float red[16];
    if ((b & 31) == 0) red[b >> 5] = s;
    __syncthreads();
    if (b == 0) {
        float tot = 0.f;
#pragma unroll
        for (int i = 0; i < 16; i++) tot += red[i];
        g_tnew = (tot / (float)NB) * 0.01f + 0.99f * t[0];
    }
    float st = sqrtf(fmaxf(1.0f - tl * tl, 0.0f));
    float cm = tl * cCOS_M - st * cSIN_M;
    g_cosm[b] = cm;
    g_final[b] = (tl > cTHRESH) ? cm : (tl - cMM);
}

// ---------------------------------------------------------------------------
// Kernel 5: tf32 mma.sync GEMM (128x128x16 tiles) + fused CurricularFace epilogue
// ---------------------------------------------------------------------------
__device__ __forceinline__ float f2tf(float x) {
    uint32_t r;
    asm("cvt.rna.tf32.f32 %0, %1;" : "=r"(r) : "f"(x));
    return __uint_as_float(r);
}

__device__ __forceinline__ void mma_tf32(float (&c)[4], const uint32_t (&a)[4],
                                         const uint32_t (&b)[2]) {
    asm volatile(
        "mma.sync.aligned.m16n8k8.row.col.f32.tf32.tf32.f32 "
        "{%0,%1,%2,%3}, {%4,%5,%6,%7}, {%8,%9}, {%0,%1,%2,%3};\n"
        : "+f"(c[0]), "+f"(c[1]), "+f"(c[2]), "+f"(c[3])
        : "r"(a[0]), "r"(a[1]), "r"(a[2]), "r"(a[3]), "r"(b[0]), "r"(b[1]));
}

#define BK 16
#define SPAD 20  // row stride in words; 20 mod 32 pattern -> conflict-free frag loads

__global__ __launch_bounds__(256) void k_gemm(const float* __restrict__ w,
                                              const int* __restrict__ labels,
                                              float* __restrict__ out) {
    __shared__ float As[2][128][SPAD];
    __shared__ float Bs[2][128][SPAD];

    const int tid = threadIdx.x;
    const int warp = tid >> 5;
    const int lane = tid & 31;
    const int g = lane >> 2;       // group 0..7
    const int tg = lane & 3;       // thread-in-group 0..3
    const int wm = (warp >> 2) * 64;  // warp m-offset (2 warps in m)
    const int wn = (warp & 3) * 32;   // warp n-offset (4 warps in n)

    const int bm0 = blockIdx.x * 128;  // m tile (4 tiles, fast dim -> weight reuse)
    const int c0 = blockIdx.y * 128;   // class tile

    // staging indices: 512 float4 per tile, 2 per thread (rows r and r+64)
    const int ar = tid >> 2;
    const int ak = (tid & 3) * 4;
    const int cA = min(c0 + ar, NC - 1);
    const int cB = min(c0 + ar + 64, NC - 1);

    float acc[4][4][4];
#pragma unroll
    for (int mi = 0; mi < 4; mi++)
#pragma unroll
        for (int ni = 0; ni < 4; ni++)
#pragma unroll
            for (int r = 0; r < 4; r++) acc[mi][ni][r] = 0.f;

    // prefetch tile 0
    {
        float4 ra0 = *reinterpret_cast<const float4*>(g_fn + (size_t)(bm0 + ar) * ND + ak);
        float4 ra1 = *reinterpret_cast<const float4*>(g_fn + (size_t)(bm0 + ar + 64) * ND + ak);
        float4 rb0 = *reinterpret_cast<const float4*>(w + (size_t)cA * ND + ak);
        float4 rb1 = *reinterpret_cast<const float4*>(w + (size_t)cB * ND + ak);
        float4 t0 = make_float4(f2tf(ra0.x), f2tf(ra0.y), f2tf(ra0.z), f2tf(ra0.w));
        float4 t1 = make_float4(f2tf(ra1.x), f2tf(ra1.y), f2tf(ra1.z), f2tf(ra1.w));
        float4 t2 = make_float4(f2tf(rb0.x), f2tf(rb0.y), f2tf(rb0.z), f2tf(rb0.w));
        float4 t3 = make_float4(f2tf(rb1.x), f2tf(rb1.y), f2tf(rb1.z), f2tf(rb1.w));
        *reinterpret_cast<float4*>(&As[0][ar][ak]) = t0;
        *reinterpret_cast<float4*>(&As[0][ar + 64][ak]) = t1;
        *reinterpret_cast<float4*>(&Bs[0][ar][ak]) = t2;
        *reinterpret_cast<float4*>(&Bs[0][ar + 64][ak]) = t3;
    }
    __syncthreads();

    int buf = 0;
    const int KT = ND / BK;  // 32
    for (int kt = 0; kt < KT; kt++) {
        float4 ra0, ra1, rb0, rb1;
        if (kt + 1 < KT) {
            int ko = (kt + 1) * BK + ak;
            ra0 = *reinterpret_cast<const float4*>(g_fn + (size_t)(bm0 + ar) * ND + ko);
            ra1 = *reinterpret_cast<const float4*>(g_fn + (size_t)(bm0 + ar + 64) * ND + ko);
            rb0 = *reinterpret_cast<const float4*>(w + (size_t)cA * ND + ko);
            rb1 = *reinterpret_cast<const float4*>(w + (size_t)cB * ND + ko);
        }

        float(*Asb)[SPAD] = As[buf];
        float(*Bsb)[SPAD] = Bs[buf];
#pragma unroll
        for (int ks = 0; ks < 2; ks++) {
            const int k0 = ks * 8;
            uint32_t af[4][4];
            uint32_t bf[4][2];
#pragma unroll
            for (int mi = 0; mi < 4; mi++) {
                const float* ap = &Asb[wm + mi * 16 + g][k0 + tg];
                af[mi][0] = __float_as_uint(ap[0]);
                af[mi][1] = __float_as_uint(ap[8 * SPAD]);
                af[mi][2] = __float_as_uint(ap[4]);
                af[mi][3] = __float_as_uint(ap[8 * SPAD + 4]);
            }
#pragma unroll
            for (int ni = 0; ni < 4; ni++) {
                const float* bp = &Bsb[wn + ni * 8 + g][k0 + tg];
                bf[ni][0] = __float_as_uint(bp[0]);
                bf[ni][1] = __float_as_uint(bp[4]);
            }
#pragma unroll
            for (int mi = 0; mi < 4; mi++)
#pragma unroll
                for (int ni = 0; ni < 4; ni++) mma_tf32(acc[mi][ni], af[mi], bf[ni]);
        }

        if (kt + 1 < KT) {
            int nb = buf ^ 1;
            float4 t0 = make_float4(f2tf(ra0.x), f2tf(ra0.y), f2tf(ra0.z), f2tf(ra0.w));
            float4 t1 = make_float4(f2tf(ra1.x), f2tf(ra1.y), f2tf(ra1.z), f2tf(ra1.w));
            float4 t2 = make_float4(f2tf(rb0.x), f2tf(rb0.y), f2tf(rb0.z), f2tf(rb0.w));
            float4 t3 = make_float4(f2tf(rb1.x), f2tf(rb1.y), f2tf(rb1.z), f2tf(rb1.w));
            *reinterpret_cast<float4*>(&As[nb][ar][ak]) = t0;
            *reinterpret_cast<float4*>(&As[nb][ar + 64][ak]) = t1;
            *reinterpret_cast<float4*>(&Bs[nb][ar][ak]) = t2;
            *reinterpret_cast<float4*>(&Bs[nb][ar + 64][ak]) = t3;
        }
        __syncthreads();
        buf ^= 1;
    }

    // ---- fused CurricularFace epilogue ----
    const float tnew = g_tnew;
    int ccol[4];
    float2 iw[4];
#pragma unroll
    for (int ni = 0; ni < 4; ni++) {
        int c = c0 + wn + ni * 8 + 2 * tg;
        ccol[ni] = c;
        iw[ni].x = g_invw[min(c, NC - 1)];
        iw[ni].y = g_invw[min(c + 1, NC - 1)];
    }
#pragma unroll
    for (int mi = 0; mi < 4; mi++) {
#pragma unroll
        for (int h = 0; h < 2; h++) {
            int m = bm0 + wm + mi * 16 + g + h * 8;
            int lab = labels[m];
            float cm = g_cosm[m];
            float fi = g_final[m];
            float* orow = out + (size_t)m * NC;
#pragma unroll
            for (int ni = 0; ni < 4; ni++) {
                int c = ccol[ni];
                if (c < NC) {
                    float x0 = acc[mi][ni][h * 2 + 0] * iw[ni].x;
                    float x1 = acc[mi][ni][h * 2 + 1] * iw[ni].y;
                    x0 = fminf(fmaxf(x0, -1.0f), 1.0f);
                    x1 = fminf(fmaxf(x1, -1.0f), 1.0f);
                    float v0 = (x0 > cm) ? x0 * (tnew + x0) : x0;
                    float v1 = (x1 > cm) ? x1 * (tnew + x1) : x1;
                    if (lab == c) v0 = fi;
                    if (lab == c + 1) v1 = fi;
                    float2 o;
                    o.x = v0 * cS;
                    o.y = v1 * cS;
                    *reinterpret_cast<float2*>(orow + c) = o;
                }
            }
        }
    }
}

// ---------------------------------------------------------------------------
extern "C" void kernel_launch(void* const* d_in, const int* in_sizes, int n_in,
                              void* d_out, int out_size) {
    const float* feats = (const float*)d_in[0];
    const int* labels = (const int*)d_in[1];
    const float* weight = (const float*)d_in[2];
    const float* t = (const float*)d_in[3];
    float* out = (float*)d_out;

    k_norm_feats<<<NB, 128>>>(feats);
    k_wnorm<<<(NC + 7) / 8, 256>>>(weight);
    k_target<<<NB, 128>>>(weight, labels);
    k_scalars<<<1, NB>>>(t);

    dim3 grid(4, (NC + 127) / 128);  // x = m-tile (fast) so 4 m-blocks share a weight tile
    k_gemm<<<grid, 256>>>(weight, labels, out);
}